// round 11
// baseline (speedup 1.0000x reference)
#include <cuda_runtime.h>
#include <cuda_fp16.h>
#include <cstdint>

#define LSZ 6400
#define WDIM 80
#define NEGV -1e9f

// Output layout (float32), total 448000:
//   [0..12800) mkpts0, [12800..25600) mkpts1, [25600..32000) mask_v,
//   [32000..38400) score, [38400..448000) sa_ir_up [640][640]

__device__ unsigned long long g_rowpack[LSZ];
__device__ unsigned int       g_colmax[LSZ];
__device__ int g_cntR, g_cntC;
__device__ unsigned g_done;
__device__ int g_rowidx[LSZ];
__device__ int g_colidx[LSZ];
// fp16 fragment-ordered compacted operands, scale 1/sqrt(6.4) folded, hi/lo split.
// g_pA4: [mt 400][ks 4][p 2][lane 32] uint4 ; g_pB2: [nt 800][ks 4][p 2][lane 32] uint2
__device__ __align__(16) uint4 g_pA4[102400];
__device__ __align__(16) uint2 g_pB2[204800];

__device__ __forceinline__ unsigned fenc(float f) {
    unsigned u = __float_as_uint(f);
    return (u & 0x80000000u) ? ~u : (u | 0x80000000u);
}
__device__ __forceinline__ float fdec(unsigned e) {
    return __uint_as_float((e & 0x80000000u) ? (e ^ 0x80000000u) : ~e);
}
__device__ __forceinline__ uint32_t smem_u32(const void* p) {
    uint32_t a;
    asm("{ .reg .u64 t; cvta.to.shared.u64 t, %1; cvt.u32.u64 %0, t; }" : "=r"(a) : "l"(p));
    return a;
}
__device__ __forceinline__ void cpa16(uint32_t dst, const void* src) {
    asm volatile("cp.async.cg.shared.global [%0], [%1], 16;" :: "r"(dst), "l"(src) : "memory");
}
__device__ __forceinline__ void mma_fp16(float* c, uint4 a, uint2 b) {
    asm volatile(
        "mma.sync.aligned.m16n8k16.row.col.f32.f16.f16.f32 "
        "{%0,%1,%2,%3}, {%4,%5,%6,%7}, {%8,%9}, {%0,%1,%2,%3};"
        : "+f"(c[0]), "+f"(c[1]), "+f"(c[2]), "+f"(c[3])
        : "r"(a.x), "r"(a.y), "r"(a.z), "r"(a.w), "r"(b.x), "r"(b.y));
}
__device__ __forceinline__ void split2(float v0, float v1, unsigned& h, unsigned& l) {
    __half h0 = __float2half_rn(v0), h1 = __float2half_rn(v1);
    __half l0 = __float2half_rn(v0 - __half2float(h0));
    __half l1 = __float2half_rn(v1 - __half2float(h1));
    h = (unsigned)__half_as_ushort(h0) | ((unsigned)__half_as_ushort(h1) << 16);
    l = (unsigned)__half_as_ushort(l0) | ((unsigned)__half_as_ushort(l1) << 16);
}

// block 0: compact rows; block 1: compact cols; blocks 2..26: zero-init + mkpts0
__global__ __launch_bounds__(256) void compact_kernel(const float* __restrict__ saV,
                                                      const float* __restrict__ saI,
                                                      float* __restrict__ out) {
    int b = blockIdx.x, tid = threadIdx.x;
    if (b < 2) {
        const float* sa = b ? saI : saV;
        int* idxout = b ? g_colidx : g_rowidx;
        __shared__ int wsum[8];
        int lane = tid & 31, w = tid >> 5;
        int base = tid * 25;
        unsigned mk = 0; int cnt = 0;
        #pragma unroll
        for (int k = 0; k < 25; ++k)
            if (sa[base + k] > 0.f) { mk |= (1u << k); ++cnt; }
        int pre = cnt;
        #pragma unroll
        for (int off = 1; off < 32; off <<= 1) {
            int n = __shfl_up_sync(0xFFFFFFFFu, pre, off);
            if (lane >= off) pre += n;
        }
        if (lane == 31) wsum[w] = pre;
        __syncthreads();
        int wbase = 0;
        for (int k = 0; k < w; ++k) wbase += wsum[k];
        int off = wbase + pre - cnt;
        #pragma unroll
        for (int k = 0; k < 25; ++k)
            if ((mk >> k) & 1u) idxout[off++] = base + k;
        if (tid == 255) { if (b) g_cntC = wbase + pre; else g_cntR = wbase + pre; }
    } else {
        int i = (b - 2) * 256 + tid;
        if (i < LSZ) {
            g_rowpack[i] = 0ull;
            g_colmax[i] = 0u;
            out[2 * i]     = (float)((i % WDIM) * 8);
            out[2 * i + 1] = (float)((i / WDIM) * 8);
        }
        if (b == 2 && tid == 0) g_done = 0u;
    }
}

// blocks 0..199: A frags; 200..599: B frags; 600..999: upsample (float4)
__global__ __launch_bounds__(256) void prep_kernel(const float* __restrict__ fA,
                                                   const float* __restrict__ fB,
                                                   const float* __restrict__ saIR,
                                                   float* __restrict__ out) {
    const float s = 0.3952847075210474f;   // 1/sqrt(6.4)
    int b = blockIdx.x, tid = threadIdx.x;
    if (b < 200) {
        int cntR = g_cntR;
        int nmt = ((cntR + 127) >> 7) * 8;
        if (2 * b >= nmt) return;
        int idx = b * 256 + tid;
        int lane = idx & 31, ks = (idx >> 5) & 3, mt = idx >> 7;
        int gid = lane >> 2, tig = lane & 3;
        int s0 = mt * 16 + gid, s1 = s0 + 8;
        int l0 = (s0 < cntR) ? g_rowidx[s0] : 0;
        int l1 = (s1 < cntR) ? g_rowidx[s1] : 0;
        int k0 = ks * 16 + 2 * tig;
        uint4 H, L;
        split2(fA[k0 * LSZ + l0] * s,       fA[(k0 + 1) * LSZ + l0] * s, H.x, L.x);
        split2(fA[k0 * LSZ + l1] * s,       fA[(k0 + 1) * LSZ + l1] * s, H.y, L.y);
        split2(fA[(k0 + 8) * LSZ + l0] * s, fA[(k0 + 9) * LSZ + l0] * s, H.z, L.z);
        split2(fA[(k0 + 8) * LSZ + l1] * s, fA[(k0 + 9) * LSZ + l1] * s, H.w, L.w);
        int base = ((mt * 4 + ks) * 2) * 32 + lane;
        g_pA4[base] = H;
        g_pA4[base + 32] = L;
    } else if (b < 600) {
        int cntC = g_cntC;
        int nnt = ((cntC + 63) >> 6) * 8;
        if (2 * (b - 200) >= nnt) return;
        int idx = (b - 200) * 256 + tid;
        int lane = idx & 31, ks = (idx >> 5) & 3, nt = idx >> 7;
        int gid = lane >> 2, tig = lane & 3;
        int sl = nt * 8 + gid;
        int n0 = (sl < cntC) ? g_colidx[sl] : 0;
        int k0 = ks * 16 + 2 * tig;
        uint2 H, L;
        split2(fB[k0 * LSZ + n0] * s,       fB[(k0 + 1) * LSZ + n0] * s, H.x, L.x);
        split2(fB[(k0 + 8) * LSZ + n0] * s, fB[(k0 + 9) * LSZ + n0] * s, H.y, L.y);
        int base = ((nt * 4 + ks) * 2) * 32 + lane;
        g_pB2[base] = H;
        g_pB2[base + 32] = L;
    } else {
        int idx4 = (b - 600) * 256 + tid;            // 0..102399, 4 outputs each
        int oy = idx4 / 160, ox4 = idx4 - oy * 160;
        float fy = (float)(oy * 79) / 639.0f;
        int y0 = (int)floorf(fy); int y1 = min(y0 + 1, 79); float wy = fy - (float)y0;
        const float* r0p = saIR + y0 * WDIM;
        const float* r1p = saIR + y1 * WDIM;
        float4 res;
        float* rp = (float*)&res;
        #pragma unroll
        for (int q = 0; q < 4; ++q) {
            int ox = ox4 * 4 + q;
            float fx = (float)(ox * 79) / 639.0f;
            int x0 = (int)floorf(fx); int x1 = min(x0 + 1, 79); float wx = fx - (float)x0;
            float a = r0p[x0] * (1.f - wy) + r1p[x0] * wy;
            float bb = r0p[x1] * (1.f - wy) + r1p[x1] * wy;
            rp[q] = a * (1.f - wx) + bb * wx;
        }
        *(float4*)(out + 38400 + idx4 * 4) = res;
    }
}

// -------- per-stage smem layout (bytes): A 32768 | B 16384 | scid 256 | scol 256
#define STG      49664
#define SM_TOTAL (2 * STG)

__global__ __launch_bounds__(256, 2)
void gemm_kernel(float* __restrict__ out) {
    extern __shared__ char smem[];
    const uint32_t sb = smem_u32(smem);
    const int cntR = g_cntR, cntC = g_cntC;
    const int nRt = (cntR + 127) >> 7, nCt = (cntC + 63) >> 6;
    const int nT = nRt * nCt;
    const int tid = threadIdx.x;
    const int w = tid >> 5, lane = tid & 31;
    const int wm = w >> 1, wn = w & 1;
    const int gid = lane >> 2, tig = lane & 3;

    int t = (int)blockIdx.x;
    int s = 0;

    // prologue prefetch
    if (t < nT) {
        int rt = t / nCt, ct = t - rt * nCt;
        const char* gA = (const char*)g_pA4 + (size_t)rt * 32768;
        const char* gB = (const char*)g_pB2 + (size_t)ct * 16384;
        #pragma unroll
        for (int c = 0; c < 8; ++c) cpa16(sb + (c * 256 + tid) * 16, gA + (c * 256 + tid) * 16);
        #pragma unroll
        for (int c = 0; c < 4; ++c) cpa16(sb + 32768 + (c * 256 + tid) * 16, gB + (c * 256 + tid) * 16);
        if (tid < 64) {
            int j = ct * 64 + tid;
            *(int*)(smem + 49152 + tid * 4) = (j < cntC) ? g_colidx[j] : 0;
            *(unsigned*)(smem + 49408 + tid * 4) = 0u;
        }
    }
    asm volatile("cp.async.commit_group;" ::: "memory");

    for (; t < nT; t += (int)gridDim.x) {
        int tn = t + (int)gridDim.x;
        if (tn < nT) {
            int rt = tn / nCt, ct = tn - rt * nCt;
            const char* gA = (const char*)g_pA4 + (size_t)rt * 32768;
            const char* gB = (const char*)g_pB2 + (size_t)ct * 16384;
            uint32_t st = sb + (s ^ 1) * STG;
            #pragma unroll
            for (int c = 0; c < 8; ++c) cpa16(st + (c * 256 + tid) * 16, gA + (c * 256 + tid) * 16);
            #pragma unroll
            for (int c = 0; c < 4; ++c) cpa16(st + 32768 + (c * 256 + tid) * 16, gB + (c * 256 + tid) * 16);
            if (tid < 64) {
                int j = ct * 64 + tid;
                *(int*)(smem + (s ^ 1) * STG + 49152 + tid * 4) = (j < cntC) ? g_colidx[j] : 0;
                *(unsigned*)(smem + (s ^ 1) * STG + 49408 + tid * 4) = 0u;
            }
        }
        asm volatile("cp.async.commit_group;" ::: "memory");
        asm volatile("cp.async.wait_group 1;" ::: "memory");
        __syncthreads();

        const int rt = t / nCt, ct = t - rt * nCt;
        const int i0 = rt * 128, j0 = ct * 64;
        const char* SA = smem + s * STG;
        const char* SB = smem + s * STG + 32768;
        const int* scid = (const int*)(smem + s * STG + 49152);
        unsigned* scol = (unsigned*)(smem + s * STG + 49408);

        float acc[2][4][4];
        #pragma unroll
        for (int m = 0; m < 2; ++m)
            #pragma unroll
            for (int nt = 0; nt < 4; ++nt)
                #pragma unroll
                for (int c = 0; c < 4; ++c) acc[m][nt][c] = 0.f;

        #pragma unroll
        for (int ks = 0; ks < 4; ++ks) {
            uint4 Ah[2], Al[2];
            #pragma unroll
            for (int m = 0; m < 2; ++m) {
                const char* ab = SA + (((2 * wm + m) * 256) + ks * 64 + lane) * 16;
                Ah[m] = *(const uint4*)ab;
                Al[m] = *(const uint4*)(ab + 512);
            }
            #pragma unroll
            for (int nt = 0; nt < 4; ++nt) {
                const char* bb = SB + (((wn * 4 + nt) * 256) + ks * 64 + lane) * 8;
                uint2 Bh = *(const uint2*)bb;
                uint2 Bl = *(const uint2*)(bb + 256);
                mma_fp16(acc[0][nt], Ah[0], Bh);
                mma_fp16(acc[1][nt], Ah[1], Bh);
                mma_fp16(acc[0][nt], Al[0], Bh);
                mma_fp16(acc[1][nt], Al[1], Bh);
                mma_fp16(acc[0][nt], Ah[0], Bl);
                mma_fp16(acc[1][nt], Ah[1], Bl);
            }
        }

        // ---- epilogue ----
        bool vcol[8]; int rcol[8];
        #pragma unroll
        for (int nt = 0; nt < 4; ++nt) {
            #pragma unroll
            for (int c = 0; c < 2; ++c) {
                int jl = wn * 32 + nt * 8 + tig * 2 + c;
                vcol[nt * 2 + c] = (j0 + jl) < cntC;
                rcol[nt * 2 + c] = scid[jl];
            }
        }
        float colm[8];
        #pragma unroll
        for (int e = 0; e < 8; ++e) colm[e] = NEGV;

        #pragma unroll
        for (int m = 0; m < 2; ++m) {
            #pragma unroll
            for (int r = 0; r < 2; ++r) {
                const int slot = i0 + wm * 32 + m * 16 + r * 8 + gid;
                const bool vr = slot < cntR;
                float rb = NEGV; int bj = 0;
                #pragma unroll
                for (int nt = 0; nt < 4; ++nt) {
                    #pragma unroll
                    for (int c = 0; c < 2; ++c) {
                        float v = acc[m][nt][r * 2 + c];
                        v = (vr && vcol[nt * 2 + c]) ? v : NEGV;
                        if (v > rb) { rb = v; bj = rcol[nt * 2 + c]; }
                        colm[nt * 2 + c] = fmaxf(colm[nt * 2 + c], v);
                    }
                }
                unsigned long long pk = ((unsigned long long)fenc(rb) << 32) | (unsigned)bj;
                #pragma unroll
                for (int off = 1; off <= 2; off <<= 1) {
                    unsigned long long o = __shfl_xor_sync(0xFFFFFFFFu, pk, off);
                    if (o > pk) pk = o;
                }
                if (tig == 0 && vr)
                    atomicMax(&g_rowpack[g_rowidx[slot]], pk);
            }
        }
        #pragma unroll
        for (int e = 0; e < 8; ++e) {
            float cm = colm[e];
            #pragma unroll
            for (int off = 4; off <= 16; off <<= 1)
                cm = fmaxf(cm, __shfl_xor_sync(0xFFFFFFFFu, cm, off));
            if (gid == 0)
                atomicMax(&scol[wn * 32 + (e >> 1) * 8 + tig * 2 + (e & 1)], fenc(cm));
        }
        __syncthreads();
        if (tid < 64 && (j0 + tid) < cntC)
            atomicMax(&g_colmax[scid[tid]], scol[tid]);
        s ^= 1;
    }

    // ---- last CTA finishes: finalize outputs ----
    __shared__ unsigned lastf;
    __syncthreads();
    __threadfence();
    if (tid == 0)
        lastf = (atomicAdd(&g_done, 1u) == gridDim.x - 1u) ? 1u : 0u;
    __syncthreads();
    if (lastf) {
        for (int i = tid; i < LSZ; i += 256) {
            unsigned long long p = g_rowpack[i];
            unsigned enc = (unsigned)(p >> 32);
            int aj = (int)(p & 0xFFFFFFFFull);
            float rm = fdec(enc);
            bool mv = (rm > 0.f) && (enc == g_colmax[aj]);
            int j = mv ? aj : 0;
            out[12800 + 2 * i]     = (float)((j % WDIM) * 8);
            out[12800 + 2 * i + 1] = (float)((j / WDIM) * 8);
            out[25600 + i] = mv ? 1.f : 0.f;
            out[32000 + i] = mv ? rm : 0.f;
        }
    }
}

extern "C" void kernel_launch(void* const* d_in, const int* in_sizes, int n_in,
                              void* d_out, int out_size) {
    const float* feat_reg_vi = (const float*)d_in[0];
    const float* feat_reg_ir = (const float*)d_in[1];
    const float* feat_sa_vi  = (const float*)d_in[2];
    const float* feat_sa_ir  = (const float*)d_in[3];
    float* out = (float*)d_out;

    cudaFuncSetAttribute(gemm_kernel, cudaFuncAttributeMaxDynamicSharedMemorySize, SM_TOTAL);

    compact_kernel<<<27, 256>>>(feat_sa_vi, feat_sa_ir, out);
    prep_kernel<<<1000, 256>>>(feat_reg_vi, feat_reg_ir, feat_sa_ir, out);
    gemm_kernel<<<296, 256, SM_TOTAL>>>(out);
}

// round 12
// speedup vs baseline: 1.0206x; 1.0206x over previous
#include <cuda_runtime.h>
#include <cuda_fp16.h>
#include <cstdint>

#define LSZ 6400
#define WDIM 80
#define NEGV -1e9f

// Output layout (float32), total 448000:
//   [0..12800) mkpts0, [12800..25600) mkpts1, [25600..32000) mask_v,
//   [32000..38400) score, [38400..448000) sa_ir_up [640][640]

__device__ unsigned long long g_rowpack[LSZ];
__device__ unsigned int       g_colmax[LSZ];
__device__ int g_cntR, g_cntC;
__device__ unsigned g_done;
__device__ int g_rowidx[LSZ];
__device__ int g_colidx[LSZ];
// fp16 fragment-ordered compacted operands, scale 1/sqrt(6.4) folded, hi/lo split.
// g_pA4: [mt 400][ks 4][p 2][lane 32] uint4 ; g_pB2: [nt 800][ks 4][p 2][lane 32] uint2
__device__ __align__(16) uint4 g_pA4[102400];
__device__ __align__(16) uint2 g_pB2[204800];

__device__ __forceinline__ unsigned fenc(float f) {
    unsigned u = __float_as_uint(f);
    return (u & 0x80000000u) ? ~u : (u | 0x80000000u);
}
__device__ __forceinline__ float fdec(unsigned e) {
    return __uint_as_float((e & 0x80000000u) ? (e ^ 0x80000000u) : ~e);
}
__device__ __forceinline__ uint32_t smem_u32(const void* p) {
    uint32_t a;
    asm("{ .reg .u64 t; cvta.to.shared.u64 t, %1; cvt.u32.u64 %0, t; }" : "=r"(a) : "l"(p));
    return a;
}
__device__ __forceinline__ void cpa16(uint32_t dst, const void* src) {
    asm volatile("cp.async.cg.shared.global [%0], [%1], 16;" :: "r"(dst), "l"(src) : "memory");
}
__device__ __forceinline__ void mma_fp16(float* c, uint4 a, uint2 b) {
    asm volatile(
        "mma.sync.aligned.m16n8k16.row.col.f32.f16.f16.f32 "
        "{%0,%1,%2,%3}, {%4,%5,%6,%7}, {%8,%9}, {%0,%1,%2,%3};"
        : "+f"(c[0]), "+f"(c[1]), "+f"(c[2]), "+f"(c[3])
        : "r"(a.x), "r"(a.y), "r"(a.z), "r"(a.w), "r"(b.x), "r"(b.y));
}
__device__ __forceinline__ void split2(float v0, float v1, unsigned& h, unsigned& l) {
    __half h0 = __float2half_rn(v0), h1 = __float2half_rn(v1);
    __half l0 = __float2half_rn(v0 - __half2float(h0));
    __half l1 = __float2half_rn(v1 - __half2float(h1));
    h = (unsigned)__half_as_ushort(h0) | ((unsigned)__half_as_ushort(h1) << 16);
    l = (unsigned)__half_as_ushort(l0) | ((unsigned)__half_as_ushort(l1) << 16);
}

// block 0: compact rows; block 1: compact cols; blocks 2..26: zero-init + mkpts0
__global__ __launch_bounds__(256) void compact_kernel(const float* __restrict__ saV,
                                                      const float* __restrict__ saI,
                                                      float* __restrict__ out) {
    int b = blockIdx.x, tid = threadIdx.x;
    if (b < 2) {
        const float* sa = b ? saI : saV;
        int* idxout = b ? g_colidx : g_rowidx;
        __shared__ int bcnt[25][8];
        int lane = tid & 31, w = tid >> 5;
        unsigned blt[25];
        #pragma unroll
        for (int k = 0; k < 25; ++k) {
            int v = sa[k * 256 + tid] > 0.f;           // coalesced
            blt[k] = __ballot_sync(0xFFFFFFFFu, v);
            if (lane == 0) bcnt[k][w] = __popc(blt[k]);
        }
        __syncthreads();
        int run = 0;
        unsigned lmask = (1u << lane) - 1u;
        #pragma unroll
        for (int k = 0; k < 25; ++k) {
            int ct = 0, wb = 0;
            #pragma unroll
            for (int q = 0; q < 8; ++q) {
                int c = bcnt[k][q];
                ct += c;
                if (q < w) wb += c;
            }
            if ((blt[k] >> lane) & 1u)
                idxout[run + wb + __popc(blt[k] & lmask)] = k * 256 + tid;
            run += ct;
        }
        if (tid == 0) { if (b) g_cntC = run; else g_cntR = run; }
    } else {
        int i = (b - 2) * 256 + tid;
        if (i < LSZ) {
            g_rowpack[i] = 0ull;
            g_colmax[i] = 0u;
            out[2 * i]     = (float)((i % WDIM) * 8);
            out[2 * i + 1] = (float)((i / WDIM) * 8);
        }
        if (b == 2 && tid == 0) g_done = 0u;
    }
}

// blocks 0..199: A frags; 200..599: B frags; 600..999: upsample (float4)
__global__ __launch_bounds__(256) void prep_kernel(const float* __restrict__ fA,
                                                   const float* __restrict__ fB,
                                                   const float* __restrict__ saIR,
                                                   float* __restrict__ out) {
    const float s = 0.3952847075210474f;   // 1/sqrt(6.4)
    int b = blockIdx.x, tid = threadIdx.x;
    if (b < 200) {
        int cntR = g_cntR;
        int nmt = ((cntR + 127) >> 7) * 8;
        if (2 * b >= nmt) return;
        int idx = b * 256 + tid;
        int lane = idx & 31, ks = (idx >> 5) & 3, mt = idx >> 7;
        int gid = lane >> 2, tig = lane & 3;
        int s0 = mt * 16 + gid, s1 = s0 + 8;
        int l0 = (s0 < cntR) ? g_rowidx[s0] : 0;
        int l1 = (s1 < cntR) ? g_rowidx[s1] : 0;
        int k0 = ks * 16 + 2 * tig;
        uint4 H, L;
        split2(fA[k0 * LSZ + l0] * s,       fA[(k0 + 1) * LSZ + l0] * s, H.x, L.x);
        split2(fA[k0 * LSZ + l1] * s,       fA[(k0 + 1) * LSZ + l1] * s, H.y, L.y);
        split2(fA[(k0 + 8) * LSZ + l0] * s, fA[(k0 + 9) * LSZ + l0] * s, H.z, L.z);
        split2(fA[(k0 + 8) * LSZ + l1] * s, fA[(k0 + 9) * LSZ + l1] * s, H.w, L.w);
        int base = ((mt * 4 + ks) * 2) * 32 + lane;
        g_pA4[base] = H;
        g_pA4[base + 32] = L;
    } else if (b < 600) {
        int cntC = g_cntC;
        int nnt = ((cntC + 127) >> 7) * 16;
        if (2 * (b - 200) >= nnt) return;
        int idx = (b - 200) * 256 + tid;
        int lane = idx & 31, ks = (idx >> 5) & 3, nt = idx >> 7;
        int gid = lane >> 2, tig = lane & 3;
        int sl = nt * 8 + gid;
        int n0 = (sl < cntC) ? g_colidx[sl] : 0;
        int k0 = ks * 16 + 2 * tig;
        uint2 H, L;
        split2(fB[k0 * LSZ + n0] * s,       fB[(k0 + 1) * LSZ + n0] * s, H.x, L.x);
        split2(fB[(k0 + 8) * LSZ + n0] * s, fB[(k0 + 9) * LSZ + n0] * s, H.y, L.y);
        int base = ((nt * 4 + ks) * 2) * 32 + lane;
        g_pB2[base] = H;
        g_pB2[base + 32] = L;
    } else {
        int idx4 = (b - 600) * 256 + tid;            // 0..102399, 4 outputs each
        int oy = idx4 / 160, ox4 = idx4 - oy * 160;
        float fy = (float)(oy * 79) / 639.0f;
        int y0 = (int)floorf(fy); int y1 = min(y0 + 1, 79); float wy = fy - (float)y0;
        const float* r0p = saIR + y0 * WDIM;
        const float* r1p = saIR + y1 * WDIM;
        float4 res;
        float* rp = (float*)&res;
        #pragma unroll
        for (int q = 0; q < 4; ++q) {
            int ox = ox4 * 4 + q;
            float fx = (float)(ox * 79) / 639.0f;
            int x0 = (int)floorf(fx); int x1 = min(x0 + 1, 79); float wx = fx - (float)x0;
            float a = r0p[x0] * (1.f - wy) + r1p[x0] * wy;
            float bb = r0p[x1] * (1.f - wy) + r1p[x1] * wy;
            rp[q] = a * (1.f - wx) + bb * wx;
        }
        *(float4*)(out + 38400 + idx4 * 4) = res;
    }
}

// -------- smem layout (bytes) --------
#define SM_A     0        // 32768
#define SM_B     32768    // 32768
#define SM_SCOL  65536    // 128 u32
#define SM_SCID  66048    // 128 u32 (real col indices)
#define SM_TOTAL 66560

__global__ __launch_bounds__(256, 2)
void gemm_kernel(float* __restrict__ out) {
    const int cntR = g_cntR, cntC = g_cntC;
    const int nRt = (cntR + 127) >> 7, nCt = (cntC + 127) >> 7;
    const int tid = threadIdx.x;
    const bool active = ((int)blockIdx.y < nRt) && ((int)blockIdx.x < nCt);

    if (active) {
        extern __shared__ char smem[];
        const uint32_t sb = smem_u32(smem);
        const int w = tid >> 5, lane = tid & 31;
        const int wm = w >> 1, wn = w & 1;
        const int gid = lane >> 2, tig = lane & 3;
        const int i0 = blockIdx.y * 128, j0 = blockIdx.x * 128;

        const char* gA = (const char*)g_pA4 + blockIdx.y * 32768;
        const char* gB = (const char*)g_pB2 + blockIdx.x * 32768;

        #pragma unroll 1
        for (int c = tid; c < 2048; c += 256) cpa16(sb + SM_A + c * 16, gA + c * 16);
        #pragma unroll 1
        for (int c = tid; c < 2048; c += 256) cpa16(sb + SM_B + c * 16, gB + c * 16);
        asm volatile("cp.async.commit_group;" ::: "memory");

        if (tid < 128) {
            ((unsigned*)(smem + SM_SCOL))[tid] = 0u;
            ((int*)(smem + SM_SCID))[tid] = (j0 + tid < cntC) ? g_colidx[j0 + tid] : 0;
        }

        float acc[2][8][4];
        #pragma unroll
        for (int m = 0; m < 2; ++m)
            #pragma unroll
            for (int nt = 0; nt < 8; ++nt)
                #pragma unroll
                for (int c = 0; c < 4; ++c) acc[m][nt][c] = 0.f;

        asm volatile("cp.async.wait_group 0;" ::: "memory");
        __syncthreads();

        #pragma unroll
        for (int ks = 0; ks < 4; ++ks) {
            uint4 Ah[2], Al[2];
            #pragma unroll
            for (int m = 0; m < 2; ++m) {
                const char* ab = smem + SM_A + (((2 * wm + m) * 256) + ks * 64 + lane) * 16;
                Ah[m] = *(const uint4*)ab;
                Al[m] = *(const uint4*)(ab + 512);
            }
            #pragma unroll
            for (int nt = 0; nt < 8; ++nt) {
                const char* bb = smem + SM_B + (((wn * 8 + nt) * 256) + ks * 64 + lane) * 8;
                uint2 Bh = *(const uint2*)bb;
                uint2 Bl = *(const uint2*)(bb + 256);
                mma_fp16(acc[0][nt], Ah[0], Bh);
                mma_fp16(acc[1][nt], Ah[1], Bh);
                mma_fp16(acc[0][nt], Al[0], Bh);
                mma_fp16(acc[1][nt], Al[1], Bh);
                mma_fp16(acc[0][nt], Ah[0], Bl);
                mma_fp16(acc[1][nt], Ah[1], Bl);
            }
        }

        // ---- epilogue: bounds-mask, row argmax (scatter), col max (scatter) ----
        unsigned* scol = (unsigned*)(smem + SM_SCOL);
        const int* scid = (const int*)(smem + SM_SCID);

        bool vcol[16];
        int rcol[16];
        #pragma unroll
        for (int nt = 0; nt < 8; ++nt) {
            #pragma unroll
            for (int c = 0; c < 2; ++c) {
                int jl = wn * 64 + nt * 8 + tig * 2 + c;
                vcol[nt * 2 + c] = (j0 + jl) < cntC;
                rcol[nt * 2 + c] = scid[jl];
            }
        }
        float colm[16];
        #pragma unroll
        for (int e = 0; e < 16; ++e) colm[e] = NEGV;

        #pragma unroll
        for (int m = 0; m < 2; ++m) {
            #pragma unroll
            for (int r = 0; r < 2; ++r) {
                const int slot = i0 + wm * 32 + m * 16 + r * 8 + gid;
                const bool vr = slot < cntR;
                float rb = NEGV; int bj = 0;
                #pragma unroll
                for (int nt = 0; nt < 8; ++nt) {
                    #pragma unroll
                    for (int c = 0; c < 2; ++c) {
                        float v = acc[m][nt][r * 2 + c];
                        v = (vr && vcol[nt * 2 + c]) ? v : NEGV;
                        if (v > rb) { rb = v; bj = rcol[nt * 2 + c]; }
                        colm[nt * 2 + c] = fmaxf(colm[nt * 2 + c], v);
                    }
                }
                unsigned long long pk = ((unsigned long long)fenc(rb) << 32) | (unsigned)bj;
                #pragma unroll
                for (int off = 1; off <= 2; off <<= 1) {
                    unsigned long long o = __shfl_xor_sync(0xFFFFFFFFu, pk, off);
                    if (o > pk) pk = o;
                }
                if (tig == 0 && vr)
                    atomicMax(&g_rowpack[g_rowidx[slot]], pk);
            }
        }
        #pragma unroll
        for (int e = 0; e < 16; ++e) {
            float cm = colm[e];
            #pragma unroll
            for (int off = 4; off <= 16; off <<= 1)
                cm = fmaxf(cm, __shfl_xor_sync(0xFFFFFFFFu, cm, off));
            if (gid == 0)
                atomicMax(&scol[wn * 64 + (e >> 1) * 8 + tig * 2 + (e & 1)], fenc(cm));
        }
        __syncthreads();
        if (tid < 128 && (j0 + tid) < cntC)
            atomicMax(&g_colmax[scid[tid]], scol[tid]);
    }

    // ---- all blocks count; last block finalizes outputs ----
    __shared__ unsigned lastf;
    __threadfence();
    if (tid == 0)
        lastf = (atomicAdd(&g_done, 1u) == gridDim.x * gridDim.y - 1u) ? 1u : 0u;
    __syncthreads();
    if (lastf) {
        __threadfence();
        for (int i = tid; i < LSZ; i += 256) {
            unsigned long long p = g_rowpack[i];
            unsigned enc = (unsigned)(p >> 32);
            int aj = (int)(p & 0xFFFFFFFFull);
            float rm = fdec(enc);
            bool mv = (rm > 0.f) && (enc == g_colmax[aj]);
            int j = mv ? aj : 0;
            out[12800 + 2 * i]     = (float)((j % WDIM) * 8);
            out[12800 + 2 * i + 1] = (float)((j / WDIM) * 8);
            out[25600 + i] = mv ? 1.f : 0.f;
            out[32000 + i] = mv ? rm : 0.f;
        }
    }
}

extern "C" void kernel_launch(void* const* d_in, const int* in_sizes, int n_in,
                              void* d_out, int out_size) {
    const float* feat_reg_vi = (const float*)d_in[0];
    const float* feat_reg_ir = (const float*)d_in[1];
    const float* feat_sa_vi  = (const float*)d_in[2];
    const float* feat_sa_ir  = (const float*)d_in[3];
    float* out = (float*)d_out;

    cudaFuncSetAttribute(gemm_kernel, cudaFuncAttributeMaxDynamicSharedMemorySize, SM_TOTAL);

    compact_kernel<<<27, 256>>>(feat_sa_vi, feat_sa_ir, out);
    prep_kernel<<<1000, 256>>>(feat_reg_vi, feat_reg_ir, feat_sa_ir, out);
    gemm_kernel<<<dim3(50, 50), 256, SM_TOTAL>>>(out);
}

// round 13
// speedup vs baseline: 1.5621x; 1.5306x over previous
#include <cuda_runtime.h>
#include <cuda_fp16.h>
#include <cstdint>

#define LSZ 6400
#define WDIM 80
#define NEGV -1e9f

// Output layout (float32), total 448000:
//   [0..12800) mkpts0, [12800..25600) mkpts1, [25600..32000) mask_v,
//   [32000..38400) score, [38400..448000) sa_ir_up [640][640]

__device__ unsigned long long g_rowpack[LSZ];
__device__ unsigned int       g_colmax[LSZ];
__device__ int g_cntR, g_cntC;
__device__ int g_rowidx[LSZ];
__device__ int g_colidx[LSZ];
// fp16 fragment-ordered compacted operands, scale 1/sqrt(6.4) folded, hi/lo split.
// g_pA4: [mt 400][ks 4][p 2][lane 32] uint4 ; g_pB2: [nt 800][ks 4][p 2][lane 32] uint2
__device__ __align__(16) uint4 g_pA4[102400];
__device__ __align__(16) uint2 g_pB2[204800];

__device__ __forceinline__ unsigned fenc(float f) {
    unsigned u = __float_as_uint(f);
    return (u & 0x80000000u) ? ~u : (u | 0x80000000u);
}
__device__ __forceinline__ float fdec(unsigned e) {
    return __uint_as_float((e & 0x80000000u) ? (e ^ 0x80000000u) : ~e);
}
__device__ __forceinline__ void mma_fp16(float* c, uint4 a, uint2 b) {
    asm volatile(
        "mma.sync.aligned.m16n8k16.row.col.f32.f16.f16.f32 "
        "{%0,%1,%2,%3}, {%4,%5,%6,%7}, {%8,%9}, {%0,%1,%2,%3};"
        : "+f"(c[0]), "+f"(c[1]), "+f"(c[2]), "+f"(c[3])
        : "r"(a.x), "r"(a.y), "r"(a.z), "r"(a.w), "r"(b.x), "r"(b.y));
}
__device__ __forceinline__ void split2(float v0, float v1, unsigned& h, unsigned& l) {
    __half h0 = __float2half_rn(v0), h1 = __float2half_rn(v1);
    __half l0 = __float2half_rn(v0 - __half2float(h0));
    __half l1 = __float2half_rn(v1 - __half2float(h1));
    h = (unsigned)__half_as_ushort(h0) | ((unsigned)__half_as_ushort(h1) << 16);
    l = (unsigned)__half_as_ushort(l0) | ((unsigned)__half_as_ushort(l1) << 16);
}

// block 0: compact rows; block 1: compact cols; blocks 2..26: zero-init + mkpts0
__global__ __launch_bounds__(256) void compact_kernel(const float* __restrict__ saV,
                                                      const float* __restrict__ saI,
                                                      float* __restrict__ out) {
    int b = blockIdx.x, tid = threadIdx.x;
    if (b < 2) {
        const float* sa = b ? saI : saV;
        int* idxout = b ? g_colidx : g_rowidx;
        __shared__ int bcnt[25][8];
        int lane = tid & 31, w = tid >> 5;
        unsigned blt[25];
        #pragma unroll
        for (int k = 0; k < 25; ++k) {
            int v = sa[k * 256 + tid] > 0.f;           // coalesced
            blt[k] = __ballot_sync(0xFFFFFFFFu, v);
            if (lane == 0) bcnt[k][w] = __popc(blt[k]);
        }
        __syncthreads();
        int run = 0;
        unsigned lmask = (1u << lane) - 1u;
        #pragma unroll
        for (int k = 0; k < 25; ++k) {
            int ct = 0, wb = 0;
            #pragma unroll
            for (int q = 0; q < 8; ++q) {
                int c = bcnt[k][q];
                ct += c;
                if (q < w) wb += c;
            }
            if ((blt[k] >> lane) & 1u)
                idxout[run + wb + __popc(blt[k] & lmask)] = k * 256 + tid;
            run += ct;
        }
        if (tid == 0) { if (b) g_cntC = run; else g_cntR = run; }
    } else {
        int i = (b - 2) * 256 + tid;
        if (i < LSZ) {
            g_rowpack[i] = 0ull;
            g_colmax[i] = 0u;
            out[2 * i]     = (float)((i % WDIM) * 8);
            out[2 * i + 1] = (float)((i / WDIM) * 8);
        }
    }
}

// blocks 0..199: A frags; 200..599: B frags; 600..999: upsample (float4)
__global__ __launch_bounds__(256) void prep_kernel(const float* __restrict__ fA,
                                                   const float* __restrict__ fB,
                                                   const float* __restrict__ saIR,
                                                   float* __restrict__ out) {
    const float s = 0.3952847075210474f;   // 1/sqrt(6.4)
    int b = blockIdx.x, tid = threadIdx.x;
    if (b < 200) {
        int cntR = g_cntR;
        int nmt = ((cntR + 127) >> 7) * 8;
        if (2 * b >= nmt) return;
        int idx = b * 256 + tid;
        int lane = idx & 31, ks = (idx >> 5) & 3, mt = idx >> 7;
        int gid = lane >> 2, tig = lane & 3;
        int s0 = mt * 16 + gid, s1 = s0 + 8;
        int l0 = (s0 < cntR) ? g_rowidx[s0] : 0;
        int l1 = (s1 < cntR) ? g_rowidx[s1] : 0;
        int k0 = ks * 16 + 2 * tig;
        uint4 H, L;
        split2(fA[k0 * LSZ + l0] * s,       fA[(k0 + 1) * LSZ + l0] * s, H.x, L.x);
        split2(fA[k0 * LSZ + l1] * s,       fA[(k0 + 1) * LSZ + l1] * s, H.y, L.y);
        split2(fA[(k0 + 8) * LSZ + l0] * s, fA[(k0 + 9) * LSZ + l0] * s, H.z, L.z);
        split2(fA[(k0 + 8) * LSZ + l1] * s, fA[(k0 + 9) * LSZ + l1] * s, H.w, L.w);
        int base = ((mt * 4 + ks) * 2) * 32 + lane;
        g_pA4[base] = H;
        g_pA4[base + 32] = L;
    } else if (b < 600) {
        int cntC = g_cntC;
        int nnt = ((cntC + 127) >> 7) * 16;
        if (2 * (b - 200) >= nnt) return;
        int idx = (b - 200) * 256 + tid;
        int lane = idx & 31, ks = (idx >> 5) & 3, nt = idx >> 7;
        int gid = lane >> 2, tig = lane & 3;
        int sl = nt * 8 + gid;
        int n0 = (sl < cntC) ? g_colidx[sl] : 0;
        int k0 = ks * 16 + 2 * tig;
        uint2 H, L;
        split2(fB[k0 * LSZ + n0] * s,       fB[(k0 + 1) * LSZ + n0] * s, H.x, L.x);
        split2(fB[(k0 + 8) * LSZ + n0] * s, fB[(k0 + 9) * LSZ + n0] * s, H.y, L.y);
        int base = ((nt * 4 + ks) * 2) * 32 + lane;
        g_pB2[base] = H;
        g_pB2[base + 32] = L;
    } else {
        int idx4 = (b - 600) * 256 + tid;            // 0..102399, 4 outputs each
        int oy = idx4 / 160, ox4 = idx4 - oy * 160;
        float fy = (float)(oy * 79) / 639.0f;
        int y0 = (int)floorf(fy); int y1 = min(y0 + 1, 79); float wy = fy - (float)y0;
        const float* r0p = saIR + y0 * WDIM;
        const float* r1p = saIR + y1 * WDIM;
        float4 res;
        float* rp = (float*)&res;
        #pragma unroll
        for (int q = 0; q < 4; ++q) {
            int ox = ox4 * 4 + q;
            float fx = (float)(ox * 79) / 639.0f;
            int x0 = (int)floorf(fx); int x1 = min(x0 + 1, 79); float wx = fx - (float)x0;
            float a = r0p[x0] * (1.f - wy) + r1p[x0] * wy;
            float bb = r0p[x1] * (1.f - wy) + r1p[x1] * wy;
            rp[q] = a * (1.f - wx) + bb * wx;
        }
        *(float4*)(out + 38400 + idx4 * 4) = res;
    }
}

// Direct-LDG GEMM: fragments streamed from L2, smem only for reductions.
__global__ __launch_bounds__(256, 2)
void gemm_kernel() {
    const int cntR = g_cntR, cntC = g_cntC;
    const int nRt = (cntR + 127) >> 7, nCt = (cntC + 127) >> 7;
    if ((int)blockIdx.y >= nRt || (int)blockIdx.x >= nCt) return;

    __shared__ unsigned scol[128];
    __shared__ int scid[128];

    const int tid = threadIdx.x;
    const int w = tid >> 5, lane = tid & 31;
    const int wm = w >> 1, wn = w & 1;
    const int gid = lane >> 2, tig = lane & 3;
    const int i0 = blockIdx.y * 128, j0 = blockIdx.x * 128;

    if (tid < 128) {
        scol[tid] = 0u;
        scid[tid] = (j0 + tid < cntC) ? g_colidx[j0 + tid] : 0;
    }
    __syncthreads();

    const uint4* gA = g_pA4 + (size_t)blockIdx.y * 2048;   // 8 mt * 256 uint4
    const uint2* gB = g_pB2 + (size_t)blockIdx.x * 4096;   // 16 nt * 256 uint2

    float acc[2][8][4];
    #pragma unroll
    for (int m = 0; m < 2; ++m)
        #pragma unroll
        for (int nt = 0; nt < 8; ++nt)
            #pragma unroll
            for (int c = 0; c < 4; ++c) acc[m][nt][c] = 0.f;

    #pragma unroll
    for (int ks = 0; ks < 4; ++ks) {
        uint4 Ah[2], Al[2];
        #pragma unroll
        for (int m = 0; m < 2; ++m) {
            const uint4* ab = gA + (2 * wm + m) * 256 + ks * 64 + lane;
            Ah[m] = __ldg(ab);
            Al[m] = __ldg(ab + 32);
        }
        #pragma unroll
        for (int nt = 0; nt < 8; ++nt) {
            const uint2* bb = gB + (wn * 8 + nt) * 256 + ks * 64 + lane;
            uint2 Bh = __ldg(bb);
            uint2 Bl = __ldg(bb + 32);
            mma_fp16(acc[0][nt], Ah[0], Bh);
            mma_fp16(acc[1][nt], Ah[1], Bh);
            mma_fp16(acc[0][nt], Al[0], Bh);
            mma_fp16(acc[1][nt], Al[1], Bh);
            mma_fp16(acc[0][nt], Ah[0], Bl);
            mma_fp16(acc[1][nt], Ah[1], Bl);
        }
    }

    // ---- epilogue: bounds-mask, row argmax (scatter), col max (scatter) ----
    bool vcol[16];
    int rcol[16];
    #pragma unroll
    for (int nt = 0; nt < 8; ++nt) {
        #pragma unroll
        for (int c = 0; c < 2; ++c) {
            int jl = wn * 64 + nt * 8 + tig * 2 + c;
            vcol[nt * 2 + c] = (j0 + jl) < cntC;
            rcol[nt * 2 + c] = scid[jl];
        }
    }
    float colm[16];
    #pragma unroll
    for (int e = 0; e < 16; ++e) colm[e] = NEGV;

    #pragma unroll
    for (int m = 0; m < 2; ++m) {
        #pragma unroll
        for (int r = 0; r < 2; ++r) {
            const int slot = i0 + wm * 32 + m * 16 + r * 8 + gid;
            const bool vr = slot < cntR;
            float rb = NEGV; int bj = 0;
            #pragma unroll
            for (int nt = 0; nt < 8; ++nt) {
                #pragma unroll
                for (int c = 0; c < 2; ++c) {
                    float v = acc[m][nt][r * 2 + c];
                    v = (vr && vcol[nt * 2 + c]) ? v : NEGV;
                    if (v > rb) { rb = v; bj = rcol[nt * 2 + c]; }
                    colm[nt * 2 + c] = fmaxf(colm[nt * 2 + c], v);
                }
            }
            unsigned long long pk = ((unsigned long long)fenc(rb) << 32) | (unsigned)bj;
            #pragma unroll
            for (int off = 1; off <= 2; off <<= 1) {
                unsigned long long o = __shfl_xor_sync(0xFFFFFFFFu, pk, off);
                if (o > pk) pk = o;
            }
            if (tig == 0 && vr)
                atomicMax(&g_rowpack[g_rowidx[slot]], pk);
        }
    }
    #pragma unroll
    for (int e = 0; e < 16; ++e) {
        float cm = colm[e];
        #pragma unroll
        for (int off = 4; off <= 16; off <<= 1)
            cm = fmaxf(cm, __shfl_xor_sync(0xFFFFFFFFu, cm, off));
        if (gid == 0)
            atomicMax(&scol[wn * 64 + (e >> 1) * 8 + tig * 2 + (e & 1)], fenc(cm));
    }
    __syncthreads();
    if (tid < 128 && (j0 + tid) < cntC)
        atomicMax(&g_colmax[scid[tid]], scol[tid]);
}

__global__ void tail_kernel(float* __restrict__ out) {
    int i = blockIdx.x * blockDim.x + threadIdx.x;
    if (i >= LSZ) return;
    unsigned long long p = g_rowpack[i];
    unsigned enc = (unsigned)(p >> 32);
    int aj = (int)(p & 0xFFFFFFFFull);
    float rm = fdec(enc);
    bool mv = (rm > 0.f) && (enc == g_colmax[aj]);
    int j = mv ? aj : 0;
    out[12800 + 2 * i]     = (float)((j % WDIM) * 8);
    out[12800 + 2 * i + 1] = (float)((j / WDIM) * 8);
    out[25600 + i] = mv ? 1.f : 0.f;
    out[32000 + i] = mv ? rm : 0.f;
}

extern "C" void kernel_launch(void* const* d_in, const int* in_sizes, int n_in,
                              void* d_out, int out_size) {
    const float* feat_reg_vi = (const float*)d_in[0];
    const float* feat_reg_ir = (const float*)d_in[1];
    const float* feat_sa_vi  = (const float*)d_in[2];
    const float* feat_sa_ir  = (const float*)d_in[3];
    float* out = (float*)d_out;

    compact_kernel<<<27, 256>>>(feat_sa_vi, feat_sa_ir, out);
    prep_kernel<<<1000, 256>>>(feat_reg_vi, feat_reg_ir, feat_sa_ir, out);
    gemm_kernel<<<dim3(50, 50), 256>>>();
    tail_kernel<<<25, 256>>>(out);
}